// round 5
// baseline (speedup 1.0000x reference)
#include <cuda_runtime.h>
#include <cuda_bf16.h>

// ---------------------------------------------------------------------------
// ConversationalGraph: 2x GraphConv (D=H=64) + leaky_relu + mean-pool + linear
//   layer: out = segsum(x[src]*w -> dst) @ W_rel + b + x @ W_root
// N=100000 nodes, E=1250000 edges, 512 graphs, C=8 outputs.
// NOTE: edge_index / batch are int32 (JAX x64 disabled demotes int64).
// ---------------------------------------------------------------------------

#define NMAX 100000
#define DIM  64
#define NGRAPH 512

__device__ float g_agg1[NMAX * DIM];
__device__ float g_h1[NMAX * DIM];
__device__ float g_agg2[NMAX * DIM];
__device__ float g_pooled[NGRAPH * DIM];
__device__ float g_counts[NGRAPH];

// ---------------------------------------------------------------------------
// Zero scratch buffers (agg1, agg2, pooled, counts). float4 grid-stride.
// ---------------------------------------------------------------------------
__global__ void zero_kernel(float* agg1, float* agg2, float* pooled, float* counts,
                            int n4 /* = N*DIM/4 */) {
    int i = blockIdx.x * blockDim.x + threadIdx.x;
    float4 z = make_float4(0.f, 0.f, 0.f, 0.f);
    if (i < n4) {
        reinterpret_cast<float4*>(agg1)[i] = z;
        reinterpret_cast<float4*>(agg2)[i] = z;
    }
    if (i < NGRAPH * DIM / 4) reinterpret_cast<float4*>(pooled)[i] = z;
    if (i < NGRAPH / 4) reinterpret_cast<float4*>(counts)[i] = z;
}

// ---------------------------------------------------------------------------
// Edge scatter: agg[dst] += x[src] * w.  16 threads per edge, float4 atomics.
// ---------------------------------------------------------------------------
__global__ void edge_kernel(const float* __restrict__ x,
                            const int* __restrict__ ei,
                            const float* __restrict__ w,
                            float* __restrict__ agg, int E) {
    int idx = blockIdx.x * blockDim.x + threadIdx.x;
    int e = idx >> 4;
    int t = idx & 15;
    if (e >= E) return;
    int s = __ldg(&ei[e]);
    int d = __ldg(&ei[e + E]);
    float wt = __ldg(&w[e]);
    float4 v = *reinterpret_cast<const float4*>(x + (size_t)s * DIM + t * 4);
    float4 m = make_float4(v.x * wt, v.y * wt, v.z * wt, v.w * wt);
    atomicAdd(reinterpret_cast<float4*>(agg + (size_t)d * DIM + t * 4), m);
}

// ---------------------------------------------------------------------------
// Node kernel: out = leaky( Aagg @ Wrel + Ax @ Wroot + b )
// Treated as [N x 128] @ [128 x 64] GEMM. Block = 64 rows x 64 cols,
// 256 threads, 4x4 register micro-tile per thread, K-chunks of 16.
// If pool != 0: instead of storing rows, atomically accumulate into
// pooled[batch[row]] (mean-pool numerator).
// ---------------------------------------------------------------------------
__global__ void __launch_bounds__(256)
node_kernel(const float* __restrict__ Aagg, const float* __restrict__ Ax,
            const float* __restrict__ Wrel, const float* __restrict__ Wroot,
            const float* __restrict__ bias,
            float* __restrict__ out,
            const int* __restrict__ batch,
            float* __restrict__ pooled,
            int N, int pool) {
    __shared__ float As[16][72];   // A chunk, transposed [k][row]
    __shared__ float Ws[16][64];   // W chunk [k][col]

    const int tid = threadIdx.x;
    const int tx = tid & 15;       // col group (4 cols)
    const int ty = tid >> 4;       // row group (4 rows)
    const int rowBase = blockIdx.x * 64;

    // loader indices
    const int lr = tid >> 2;          // 0..63 : A row
    const int lc = (tid & 3) * 4;     // 0,4,8,12 : A k-offset
    const int wk = tid >> 4;          // 0..15 : W k
    const int wj = (tid & 15) * 4;    // W col

    float acc[4][4];
#pragma unroll
    for (int i = 0; i < 4; i++)
#pragma unroll
        for (int j = 0; j < 4; j++) acc[i][j] = 0.f;

#pragma unroll
    for (int kc = 0; kc < 8; kc++) {
        const int kk = (kc & 3) * 16;
        const float* Asrc = (kc < 4) ? Aagg : Ax;
        const float* Wsrc = (kc < 4) ? Wrel : Wroot;

        const int arow = rowBase + lr;
        float4 av = make_float4(0.f, 0.f, 0.f, 0.f);
        if (arow < N)
            av = *reinterpret_cast<const float4*>(Asrc + (size_t)arow * DIM + kk + lc);
        float4 wv = *reinterpret_cast<const float4*>(Wsrc + (wk + kk) * DIM + wj);

        __syncthreads();
        As[lc + 0][lr] = av.x;
        As[lc + 1][lr] = av.y;
        As[lc + 2][lr] = av.z;
        As[lc + 3][lr] = av.w;
        *reinterpret_cast<float4*>(&Ws[wk][wj]) = wv;
        __syncthreads();

#pragma unroll
        for (int k = 0; k < 16; k++) {
            float4 wq = *reinterpret_cast<float4*>(&Ws[k][tx * 4]);
            float a0 = As[k][ty * 4 + 0];
            float a1 = As[k][ty * 4 + 1];
            float a2 = As[k][ty * 4 + 2];
            float a3 = As[k][ty * 4 + 3];
            acc[0][0] += a0 * wq.x; acc[0][1] += a0 * wq.y; acc[0][2] += a0 * wq.z; acc[0][3] += a0 * wq.w;
            acc[1][0] += a1 * wq.x; acc[1][1] += a1 * wq.y; acc[1][2] += a1 * wq.z; acc[1][3] += a1 * wq.w;
            acc[2][0] += a2 * wq.x; acc[2][1] += a2 * wq.y; acc[2][2] += a2 * wq.z; acc[2][3] += a2 * wq.w;
            acc[3][0] += a3 * wq.x; acc[3][1] += a3 * wq.y; acc[3][2] += a3 * wq.z; acc[3][3] += a3 * wq.w;
        }
    }

    const float4 b4 = *reinterpret_cast<const float4*>(bias + tx * 4);
#pragma unroll
    for (int i = 0; i < 4; i++) {
        const int r = rowBase + ty * 4 + i;
        if (r >= N) continue;
        float4 v;
        v.x = acc[i][0] + b4.x;
        v.y = acc[i][1] + b4.y;
        v.z = acc[i][2] + b4.z;
        v.w = acc[i][3] + b4.w;
        // leaky relu 0.01
        v.x = (v.x > 0.f) ? v.x : 0.01f * v.x;
        v.y = (v.y > 0.f) ? v.y : 0.01f * v.y;
        v.z = (v.z > 0.f) ? v.z : 0.01f * v.z;
        v.w = (v.w > 0.f) ? v.w : 0.01f * v.w;
        if (!pool) {
            *reinterpret_cast<float4*>(out + (size_t)r * DIM + tx * 4) = v;
        } else {
            int g = batch[r];
            atomicAdd(reinterpret_cast<float4*>(pooled + (size_t)g * DIM + tx * 4), v);
        }
    }
}

// ---------------------------------------------------------------------------
// Node counts per graph
// ---------------------------------------------------------------------------
__global__ void counts_kernel(const int* __restrict__ batch,
                              float* __restrict__ counts, int N) {
    int i = blockIdx.x * blockDim.x + threadIdx.x;
    if (i < N) atomicAdd(&counts[batch[i]], 1.0f);
}

// ---------------------------------------------------------------------------
// Final: out[g] = (pooled[g]/max(count,1)) @ Wl + bl   (512 x 8)
// ---------------------------------------------------------------------------
__global__ void final_kernel(const float* __restrict__ pooled,
                             const float* __restrict__ counts,
                             const float* __restrict__ Wl,
                             const float* __restrict__ bl,
                             float* __restrict__ out) {
    int g = blockIdx.x * blockDim.x + threadIdx.x;
    if (g >= NGRAPH) return;
    float inv = 1.0f / fmaxf(counts[g], 1.0f);
    float acc[8];
#pragma unroll
    for (int c = 0; c < 8; c++) acc[c] = 0.f;
    for (int d = 0; d < DIM; d++) {
        float p = pooled[g * DIM + d];
#pragma unroll
        for (int c = 0; c < 8; c++) acc[c] += p * Wl[d * 8 + c];
    }
#pragma unroll
    for (int c = 0; c < 8; c++) out[g * 8 + c] = bl[c] + inv * acc[c];
}

// ---------------------------------------------------------------------------
extern "C" void kernel_launch(void* const* d_in, const int* in_sizes, int n_in,
                              void* d_out, int out_size) {
    const float* x      = (const float*)d_in[0];
    const int*   ei     = (const int*)d_in[1];
    const float* w      = (const float*)d_in[2];
    const int*   batch  = (const int*)d_in[3];
    const float* W1root = (const float*)d_in[4];
    const float* W1rel  = (const float*)d_in[5];
    const float* b1     = (const float*)d_in[6];
    const float* W2root = (const float*)d_in[7];
    const float* W2rel  = (const float*)d_in[8];
    const float* b2     = (const float*)d_in[9];
    const float* Wl     = (const float*)d_in[10];
    const float* bl     = (const float*)d_in[11];
    float* out = (float*)d_out;

    const int N = in_sizes[0] / DIM;
    const int E = in_sizes[2];

    float *agg1, *h1, *agg2, *pooled, *counts;
    cudaGetSymbolAddress((void**)&agg1,   g_agg1);
    cudaGetSymbolAddress((void**)&h1,     g_h1);
    cudaGetSymbolAddress((void**)&agg2,   g_agg2);
    cudaGetSymbolAddress((void**)&pooled, g_pooled);
    cudaGetSymbolAddress((void**)&counts, g_counts);

    const int n4 = N * DIM / 4;
    zero_kernel<<<(n4 + 255) / 256, 256>>>(agg1, agg2, pooled, counts, n4);

    const int edgeBlocks = (E * 16 + 255) / 256;
    const int nodeBlocks = (N + 63) / 64;

    // Layer 1
    edge_kernel<<<edgeBlocks, 256>>>(x, ei, w, agg1, E);
    node_kernel<<<nodeBlocks, 256>>>(agg1, x, W1rel, W1root, b1,
                                     h1, nullptr, nullptr, N, 0);
    // Layer 2 (pool fused into epilogue)
    edge_kernel<<<edgeBlocks, 256>>>(h1, ei, w, agg2, E);
    node_kernel<<<nodeBlocks, 256>>>(agg2, h1, W2rel, W2root, b2,
                                     nullptr, batch, pooled, N, 1);

    counts_kernel<<<(N + 255) / 256, 256>>>(batch, counts, N);
    final_kernel<<<(NGRAPH + 255) / 256, 256>>>(pooled, counts, Wl, bl, out);
}

// round 6
// speedup vs baseline: 1.1518x; 1.1518x over previous
#include <cuda_runtime.h>
#include <cuda_bf16.h>

// ---------------------------------------------------------------------------
// ConversationalGraph: 2x GraphConv (D=H=64) + leaky_relu + mean-pool + linear
//   layer: out = segsum(x[src]*w -> dst) @ W_rel + b + x @ W_root
// N=100000 nodes, E=1250000 edges, 512 graphs, C=8 outputs.
// Strategy: build dst-sorted CSR per call (counting sort), then atomic-free
// gather aggregation (1 warp/node), tiled fp32 GEMM for node updates.
// ---------------------------------------------------------------------------

#define NMAX   100000
#define EMAX   1250000
#define DIM    64
#define NGRAPH 512
#define SCANB  1024
#define NBLK   ((NMAX + SCANB - 1) / SCANB)   // 98

__device__ float g_agg[NMAX * DIM];
__device__ float g_h1[NMAX * DIM];
__device__ float g_pooled[NGRAPH * DIM];
__device__ float g_counts[NGRAPH];

__device__ int2 g_edges[EMAX];          // (src, w-bits) sorted by dst
__device__ int  g_deg[NMAX];
__device__ int  g_rowstart[NMAX + 1];
__device__ int  g_cursor[NMAX];
__device__ int  g_blocksum[NBLK + 1];

// ---------------------------------------------------------------------------
// Zero: degree histogram + pooled + counts
// ---------------------------------------------------------------------------
__global__ void zero_kernel(int* deg, float* pooled, float* counts, int N) {
    int i = blockIdx.x * blockDim.x + threadIdx.x;
    if (i < N) deg[i] = 0;
    if (i < NGRAPH * DIM) pooled[i] = 0.f;
    if (i < NGRAPH) counts[i] = 0.f;
}

// ---------------------------------------------------------------------------
// CSR build: histogram, 2-level exclusive scan, scatter
// ---------------------------------------------------------------------------
__global__ void hist_kernel(const int* __restrict__ ei, int* __restrict__ deg, int E) {
    int e = blockIdx.x * blockDim.x + threadIdx.x;
    if (e < E) atomicAdd(&deg[__ldg(&ei[e + E])], 1);
}

__global__ void scan1_kernel(const int* __restrict__ deg, int* __restrict__ rowstart,
                             int* __restrict__ blocksum, int N) {
    __shared__ int s[SCANB];
    int i = blockIdx.x * SCANB + threadIdx.x;
    int v = (i < N) ? deg[i] : 0;
    s[threadIdx.x] = v;
    __syncthreads();
#pragma unroll
    for (int off = 1; off < SCANB; off <<= 1) {
        int t = (threadIdx.x >= off) ? s[threadIdx.x - off] : 0;
        __syncthreads();
        s[threadIdx.x] += t;
        __syncthreads();
    }
    if (i < N) rowstart[i] = s[threadIdx.x] - v;   // exclusive
    if (threadIdx.x == SCANB - 1) blocksum[blockIdx.x] = s[SCANB - 1];
}

__global__ void scan2_kernel(int* __restrict__ blocksum, int nb) {
    __shared__ int s[NBLK + 1];
    if (threadIdx.x < nb) s[threadIdx.x] = blocksum[threadIdx.x];
    __syncthreads();
    if (threadIdx.x == 0) {
        int acc = 0;
        for (int b = 0; b < nb; b++) { int t = s[b]; s[b] = acc; acc += t; }
    }
    __syncthreads();
    if (threadIdx.x < nb) blocksum[threadIdx.x] = s[threadIdx.x];
}

__global__ void scan3_kernel(int* __restrict__ rowstart, int* __restrict__ cursor,
                             const int* __restrict__ blocksum, int N, int E) {
    int i = blockIdx.x * blockDim.x + threadIdx.x;
    if (i < N) {
        int r = rowstart[i] + blocksum[i >> 10];
        rowstart[i] = r;
        cursor[i] = r;
    }
    if (i == 0) rowstart[N] = E;
}

__global__ void scatter_kernel(const int* __restrict__ ei, const float* __restrict__ w,
                               int* __restrict__ cursor, int2* __restrict__ edges, int E) {
    int e = blockIdx.x * blockDim.x + threadIdx.x;
    if (e >= E) return;
    int s = __ldg(&ei[e]);
    int d = __ldg(&ei[e + E]);
    int pos = atomicAdd(&cursor[d], 1);
    edges[pos] = make_int2(s, __float_as_int(__ldg(&w[e])));
}

// ---------------------------------------------------------------------------
// Atomic-free aggregation: agg[n] = sum over incident edges of x[src]*w.
// One warp per node; lane holds cols {lane, lane+32}.
// ---------------------------------------------------------------------------
__global__ void __launch_bounds__(256)
gather_kernel(const float* __restrict__ x, const int2* __restrict__ edges,
              const int* __restrict__ rowstart, float* __restrict__ agg, int N) {
    int gtid = blockIdx.x * blockDim.x + threadIdx.x;
    int node = gtid >> 5;
    int lane = gtid & 31;
    if (node >= N) return;
    int beg = __ldg(&rowstart[node]);
    int end = __ldg(&rowstart[node + 1]);
    float a0 = 0.f, a1 = 0.f;
#pragma unroll 2
    for (int i = beg; i < end; i++) {
        int2 ed = __ldg(&edges[i]);                 // broadcast across warp
        float wt = __int_as_float(ed.y);
        const float* xr = x + (size_t)ed.x * DIM;
        a0 += wt * __ldg(xr + lane);
        a1 += wt * __ldg(xr + lane + 32);
    }
    agg[(size_t)node * DIM + lane] = a0;
    agg[(size_t)node * DIM + lane + 32] = a1;
}

// ---------------------------------------------------------------------------
// Node kernel: out = leaky( Aagg @ Wrel + Ax @ Wroot + b )
// [N x 128] @ [128 x 64] GEMM; 64x64 block tile, 4x4 micro-tile.
// pool!=0: accumulate rows into pooled[batch[row]] instead of storing.
// ---------------------------------------------------------------------------
__global__ void __launch_bounds__(256)
node_kernel(const float* __restrict__ Aagg, const float* __restrict__ Ax,
            const float* __restrict__ Wrel, const float* __restrict__ Wroot,
            const float* __restrict__ bias,
            float* __restrict__ out,
            const int* __restrict__ batch,
            float* __restrict__ pooled,
            int N, int pool) {
    __shared__ float As[16][72];
    __shared__ float Ws[16][64];

    const int tid = threadIdx.x;
    const int tx = tid & 15;
    const int ty = tid >> 4;
    const int rowBase = blockIdx.x * 64;

    const int lr = tid >> 2;
    const int lc = (tid & 3) * 4;
    const int wk = tid >> 4;
    const int wj = (tid & 15) * 4;

    float acc[4][4];
#pragma unroll
    for (int i = 0; i < 4; i++)
#pragma unroll
        for (int j = 0; j < 4; j++) acc[i][j] = 0.f;

#pragma unroll
    for (int kc = 0; kc < 8; kc++) {
        const int kk = (kc & 3) * 16;
        const float* Asrc = (kc < 4) ? Aagg : Ax;
        const float* Wsrc = (kc < 4) ? Wrel : Wroot;

        const int arow = rowBase + lr;
        float4 av = make_float4(0.f, 0.f, 0.f, 0.f);
        if (arow < N)
            av = *reinterpret_cast<const float4*>(Asrc + (size_t)arow * DIM + kk + lc);
        float4 wv = *reinterpret_cast<const float4*>(Wsrc + (wk + kk) * DIM + wj);

        __syncthreads();
        As[lc + 0][lr] = av.x;
        As[lc + 1][lr] = av.y;
        As[lc + 2][lr] = av.z;
        As[lc + 3][lr] = av.w;
        *reinterpret_cast<float4*>(&Ws[wk][wj]) = wv;
        __syncthreads();

#pragma unroll
        for (int k = 0; k < 16; k++) {
            float4 wq = *reinterpret_cast<float4*>(&Ws[k][tx * 4]);
            float a0 = As[k][ty * 4 + 0];
            float a1 = As[k][ty * 4 + 1];
            float a2 = As[k][ty * 4 + 2];
            float a3 = As[k][ty * 4 + 3];
            acc[0][0] += a0 * wq.x; acc[0][1] += a0 * wq.y; acc[0][2] += a0 * wq.z; acc[0][3] += a0 * wq.w;
            acc[1][0] += a1 * wq.x; acc[1][1] += a1 * wq.y; acc[1][2] += a1 * wq.z; acc[1][3] += a1 * wq.w;
            acc[2][0] += a2 * wq.x; acc[2][1] += a2 * wq.y; acc[2][2] += a2 * wq.z; acc[2][3] += a2 * wq.w;
            acc[3][0] += a3 * wq.x; acc[3][1] += a3 * wq.y; acc[3][2] += a3 * wq.z; acc[3][3] += a3 * wq.w;
        }
    }

    const float4 b4 = *reinterpret_cast<const float4*>(bias + tx * 4);
#pragma unroll
    for (int i = 0; i < 4; i++) {
        const int r = rowBase + ty * 4 + i;
        if (r >= N) continue;
        float4 v;
        v.x = acc[i][0] + b4.x;
        v.y = acc[i][1] + b4.y;
        v.z = acc[i][2] + b4.z;
        v.w = acc[i][3] + b4.w;
        v.x = (v.x > 0.f) ? v.x : 0.01f * v.x;
        v.y = (v.y > 0.f) ? v.y : 0.01f * v.y;
        v.z = (v.z > 0.f) ? v.z : 0.01f * v.z;
        v.w = (v.w > 0.f) ? v.w : 0.01f * v.w;
        if (!pool) {
            *reinterpret_cast<float4*>(out + (size_t)r * DIM + tx * 4) = v;
        } else {
            int g = batch[r];
            atomicAdd(reinterpret_cast<float4*>(pooled + (size_t)g * DIM + tx * 4), v);
        }
    }
}

// ---------------------------------------------------------------------------
__global__ void counts_kernel(const int* __restrict__ batch,
                              float* __restrict__ counts, int N) {
    int i = blockIdx.x * blockDim.x + threadIdx.x;
    if (i < N) atomicAdd(&counts[batch[i]], 1.0f);
}

__global__ void final_kernel(const float* __restrict__ pooled,
                             const float* __restrict__ counts,
                             const float* __restrict__ Wl,
                             const float* __restrict__ bl,
                             float* __restrict__ out) {
    int g = blockIdx.x * blockDim.x + threadIdx.x;
    if (g >= NGRAPH) return;
    float inv = 1.0f / fmaxf(counts[g], 1.0f);
    float acc[8];
#pragma unroll
    for (int c = 0; c < 8; c++) acc[c] = 0.f;
    for (int d = 0; d < DIM; d++) {
        float p = pooled[g * DIM + d];
#pragma unroll
        for (int c = 0; c < 8; c++) acc[c] += p * Wl[d * 8 + c];
    }
#pragma unroll
    for (int c = 0; c < 8; c++) out[g * 8 + c] = bl[c] + inv * acc[c];
}

// ---------------------------------------------------------------------------
extern "C" void kernel_launch(void* const* d_in, const int* in_sizes, int n_in,
                              void* d_out, int out_size) {
    const float* x      = (const float*)d_in[0];
    const int*   ei     = (const int*)d_in[1];
    const float* w      = (const float*)d_in[2];
    const int*   batch  = (const int*)d_in[3];
    const float* W1root = (const float*)d_in[4];
    const float* W1rel  = (const float*)d_in[5];
    const float* b1     = (const float*)d_in[6];
    const float* W2root = (const float*)d_in[7];
    const float* W2rel  = (const float*)d_in[8];
    const float* b2     = (const float*)d_in[9];
    const float* Wl     = (const float*)d_in[10];
    const float* bl     = (const float*)d_in[11];
    float* out = (float*)d_out;

    const int N = in_sizes[0] / DIM;
    const int E = in_sizes[2];

    float *agg, *h1, *pooled, *counts;
    int2* edges; int *deg, *rowstart, *cursor, *blocksum;
    cudaGetSymbolAddress((void**)&agg,      g_agg);
    cudaGetSymbolAddress((void**)&h1,       g_h1);
    cudaGetSymbolAddress((void**)&pooled,   g_pooled);
    cudaGetSymbolAddress((void**)&counts,   g_counts);
    cudaGetSymbolAddress((void**)&edges,    g_edges);
    cudaGetSymbolAddress((void**)&deg,      g_deg);
    cudaGetSymbolAddress((void**)&rowstart, g_rowstart);
    cudaGetSymbolAddress((void**)&cursor,   g_cursor);
    cudaGetSymbolAddress((void**)&blocksum, g_blocksum);

    const int nb = (N + SCANB - 1) / SCANB;

    // ---- CSR build (shared by both layers) ----
    zero_kernel<<<(N + 255) / 256, 256>>>(deg, pooled, counts, N);
    hist_kernel<<<(E + 255) / 256, 256>>>(ei, deg, E);
    scan1_kernel<<<nb, SCANB>>>(deg, rowstart, blocksum, N);
    scan2_kernel<<<1, 128>>>(blocksum, nb);
    scan3_kernel<<<(N + 255) / 256, 256>>>(rowstart, cursor, blocksum, N, E);
    scatter_kernel<<<(E + 255) / 256, 256>>>(ei, w, cursor, edges, E);

    const int gatherBlocks = (N * 32 + 255) / 256;
    const int nodeBlocks = (N + 63) / 64;

    // ---- Layer 1 ----
    gather_kernel<<<gatherBlocks, 256>>>(x, edges, rowstart, agg, N);
    node_kernel<<<nodeBlocks, 256>>>(agg, x, W1rel, W1root, b1,
                                     h1, nullptr, nullptr, N, 0);
    // ---- Layer 2 (pool fused into epilogue) ----
    gather_kernel<<<gatherBlocks, 256>>>(h1, edges, rowstart, agg, N);
    node_kernel<<<nodeBlocks, 256>>>(agg, h1, W2rel, W2root, b2,
                                     nullptr, batch, pooled, N, 1);

    counts_kernel<<<(N + 255) / 256, 256>>>(batch, counts, N);
    final_kernel<<<(NGRAPH + 255) / 256, 256>>>(pooled, counts, Wl, bl, out);
}

// round 9
// speedup vs baseline: 1.3734x; 1.1924x over previous
#include <cuda_runtime.h>
#include <cuda_bf16.h>
#include <cstdint>

// ---------------------------------------------------------------------------
// ConversationalGraph: 2x GraphConv (D=H=64) + leaky_relu + mean-pool + linear
//   layer: out = segsum(x[src]*w -> dst) @ W_rel + b + x @ W_root
// N=100000, E=1250000, 512 graphs, C=8.
// CSR counting-sort + atomic-free warp gather + f32x2 packed-FMA node GEMM.
// ---------------------------------------------------------------------------

#define NMAX   100000
#define EMAX   1250000
#define DIM    64
#define NGRAPH 512
#define SCANB  1024
#define NBLK   ((NMAX + SCANB - 1) / SCANB)   // 98

__device__ float g_agg[NMAX * DIM];
__device__ float g_h1[NMAX * DIM];
__device__ float g_pooled[NGRAPH * DIM];
__device__ float g_counts[NGRAPH];

__device__ int2 g_edges[EMAX];          // (src, w-bits) sorted by dst
__device__ int  g_deg[NMAX];
__device__ int  g_rowstart[NMAX + 1];
__device__ int  g_cursor[NMAX];
__device__ int  g_blocksum[NBLK + 1];

// ---- packed f32x2 helpers --------------------------------------------------
__device__ __forceinline__ uint64_t ffma2(uint64_t a, uint64_t b, uint64_t c) {
    uint64_t d;
    asm("fma.rn.f32x2 %0, %1, %2, %3;" : "=l"(d) : "l"(a), "l"(b), "l"(c));
    return d;
}
__device__ __forceinline__ uint64_t splat2(float f) {
    uint64_t d;
    asm("mov.b64 %0, {%1, %1};" : "=l"(d) : "f"(f));
    return d;
}
__device__ __forceinline__ void unpack2(uint64_t v, float& lo, float& hi) {
    asm("mov.b64 {%0, %1}, %2;" : "=f"(lo), "=f"(hi) : "l"(v));
}

// ---------------------------------------------------------------------------
__global__ void zero_kernel(int* deg, float* pooled, float* counts, int N) {
    int i = blockIdx.x * blockDim.x + threadIdx.x;
    if (i < N) deg[i] = 0;
    if (i < NGRAPH * DIM) pooled[i] = 0.f;
    if (i < NGRAPH) counts[i] = 0.f;
}

// ---------------------------------------------------------------------------
// CSR build: histogram, 2-level exclusive scan, scatter
// ---------------------------------------------------------------------------
__global__ void hist_kernel(const int* __restrict__ ei, int* __restrict__ deg, int E) {
    int e = blockIdx.x * blockDim.x + threadIdx.x;
    if (e < E) atomicAdd(&deg[__ldg(&ei[e + E])], 1);
}

__global__ void scan1_kernel(const int* __restrict__ deg, int* __restrict__ rowstart,
                             int* __restrict__ blocksum, int N) {
    __shared__ int s[SCANB];
    int i = blockIdx.x * SCANB + threadIdx.x;
    int v = (i < N) ? deg[i] : 0;
    s[threadIdx.x] = v;
    __syncthreads();
#pragma unroll
    for (int off = 1; off < SCANB; off <<= 1) {
        int t = (threadIdx.x >= off) ? s[threadIdx.x - off] : 0;
        __syncthreads();
        s[threadIdx.x] += t;
        __syncthreads();
    }
    if (i < N) rowstart[i] = s[threadIdx.x] - v;   // exclusive
    if (threadIdx.x == SCANB - 1) blocksum[blockIdx.x] = s[SCANB - 1];
}

// parallel exclusive scan over <=128 block sums (Hillis-Steele in smem)
__global__ void scan2_kernel(int* __restrict__ blocksum, int nb) {
    __shared__ int s[128];
    int t = threadIdx.x;
    int v = (t < nb) ? blocksum[t] : 0;
    s[t] = v;
    __syncthreads();
#pragma unroll
    for (int off = 1; off < 128; off <<= 1) {
        int u = (t >= off) ? s[t - off] : 0;
        __syncthreads();
        s[t] += u;
        __syncthreads();
    }
    if (t < nb) blocksum[t] = s[t] - v;   // exclusive
}

__global__ void scan3_kernel(int* __restrict__ rowstart, int* __restrict__ cursor,
                             const int* __restrict__ blocksum, int N, int E) {
    int i = blockIdx.x * blockDim.x + threadIdx.x;
    if (i < N) {
        int r = rowstart[i] + blocksum[i >> 10];
        rowstart[i] = r;
        cursor[i] = r;
    }
    if (i == 0) rowstart[N] = E;
}

__global__ void scatter_kernel(const int* __restrict__ ei, const float* __restrict__ w,
                               int* __restrict__ cursor, int2* __restrict__ edges, int E) {
    int e = blockIdx.x * blockDim.x + threadIdx.x;
    if (e >= E) return;
    int s = __ldg(&ei[e]);
    int d = __ldg(&ei[e + E]);
    int pos = atomicAdd(&cursor[d], 1);
    edges[pos] = make_int2(s, __float_as_int(__ldg(&w[e])));
}

// ---------------------------------------------------------------------------
// Atomic-free aggregation: agg[n] = sum over incident edges of x[src]*w.
// One warp per node; lane holds cols {lane, lane+32}.
// ---------------------------------------------------------------------------
__global__ void __launch_bounds__(256)
gather_kernel(const float* __restrict__ x, const int2* __restrict__ edges,
              const int* __restrict__ rowstart, float* __restrict__ agg, int N) {
    int gtid = blockIdx.x * blockDim.x + threadIdx.x;
    int node = gtid >> 5;
    int lane = gtid & 31;
    if (node >= N) return;
    int beg = __ldg(&rowstart[node]);
    int end = __ldg(&rowstart[node + 1]);
    float a0 = 0.f, a1 = 0.f;
#pragma unroll 4
    for (int i = beg; i < end; i++) {
        int2 ed = __ldg(&edges[i]);                 // broadcast across warp
        float wt = __int_as_float(ed.y);
        const float* xr = x + (size_t)ed.x * DIM;
        a0 += wt * __ldg(xr + lane);
        a1 += wt * __ldg(xr + lane + 32);
    }
    agg[(size_t)node * DIM + lane] = a0;
    agg[(size_t)node * DIM + lane + 32] = a1;
}

// ---------------------------------------------------------------------------
// Node kernel: out = leaky( Aagg @ Wrel + Ax @ Wroot + b )
// [N x 128] @ [128 x 64] GEMM via packed fma.rn.f32x2.
// Block tile 128 rows x 64 cols, 256 threads, per-thread 8x4 micro-tile
// (4 row-pairs packed in u64 x 4 cols). A row-pairs come packed from LDS.64.
// pool!=0: accumulate rows into pooled[batch[row]] instead of storing.
// ---------------------------------------------------------------------------
__global__ void __launch_bounds__(256)
node_kernel(const float* __restrict__ Aagg, const float* __restrict__ Ax,
            const float* __restrict__ Wrel, const float* __restrict__ Wroot,
            const float* __restrict__ bias,
            float* __restrict__ out,
            const int* __restrict__ batch,
            float* __restrict__ pooled,
            int N, int pool) {
    __shared__ float As[16][136];   // [k][row], 128 rows + pad
    __shared__ float Ws[16][64];    // [k][col]

    const int tid = threadIdx.x;
    const int tx = tid & 15;        // col group: cols tx*4 .. +3
    const int ty = tid >> 4;        // row group: rows ty*8 .. +7
    const int rowBase = blockIdx.x * 128;

    // A loader: row lr (0..127), k-offset lks in {0,8}
    const int lr  = tid >> 1;
    const int lks = (tid & 1) * 8;
    // W loader
    const int wk = tid >> 4;
    const int wj = (tid & 15) * 4;

    uint64_t accp[4][4];            // [row-pair][col]
#pragma unroll
    for (int p = 0; p < 4; p++)
#pragma unroll
        for (int c = 0; c < 4; c++) accp[p][c] = 0ull;

#pragma unroll
    for (int kc = 0; kc < 8; kc++) {
        const int kk = (kc & 3) * 16;
        const float* Asrc = (kc < 4) ? Aagg : Ax;
        const float* Wsrc = (kc < 4) ? Wrel : Wroot;

        const int arow = rowBase + lr;
        float4 av0 = make_float4(0.f, 0.f, 0.f, 0.f);
        float4 av1 = av0;
        if (arow < N) {
            const float* base = Asrc + (size_t)arow * DIM + kk + lks;
            av0 = *reinterpret_cast<const float4*>(base);
            av1 = *reinterpret_cast<const float4*>(base + 4);
        }
        float4 wv = *reinterpret_cast<const float4*>(Wsrc + (wk + kk) * DIM + wj);

        __syncthreads();
        As[lks + 0][lr] = av0.x;
        As[lks + 1][lr] = av0.y;
        As[lks + 2][lr] = av0.z;
        As[lks + 3][lr] = av0.w;
        As[lks + 4][lr] = av1.x;
        As[lks + 5][lr] = av1.y;
        As[lks + 6][lr] = av1.z;
        As[lks + 7][lr] = av1.w;
        *reinterpret_cast<float4*>(&Ws[wk][wj]) = wv;
        __syncthreads();

#pragma unroll
        for (int k = 0; k < 16; k++) {
            const uint64_t* arow2 =
                reinterpret_cast<const uint64_t*>(&As[k][ty * 8]);
            uint64_t ap0 = arow2[0];
            uint64_t ap1 = arow2[1];
            uint64_t ap2 = arow2[2];
            uint64_t ap3 = arow2[3];
            float4 wq = *reinterpret_cast<float4*>(&Ws[k][tx * 4]);
            uint64_t w0 = splat2(wq.x);
            uint64_t w1 = splat2(wq.y);
            uint64_t w2 = splat2(wq.z);
            uint64_t w3 = splat2(wq.w);
            accp[0][0] = ffma2(ap0, w0, accp[0][0]);
            accp[0][1] = ffma2(ap0, w1, accp[0][1]);
            accp[0][2] = ffma2(ap0, w2, accp[0][2]);
            accp[0][3] = ffma2(ap0, w3, accp[0][3]);
            accp[1][0] = ffma2(ap1, w0, accp[1][0]);
            accp[1][1] = ffma2(ap1, w1, accp[1][1]);
            accp[1][2] = ffma2(ap1, w2, accp[1][2]);
            accp[1][3] = ffma2(ap1, w3, accp[1][3]);
            accp[2][0] = ffma2(ap2, w0, accp[2][0]);
            accp[2][1] = ffma2(ap2, w1, accp[2][1]);
            accp[2][2] = ffma2(ap2, w2, accp[2][2]);
            accp[2][3] = ffma2(ap2, w3, accp[2][3]);
            accp[3][0] = ffma2(ap3, w0, accp[3][0]);
            accp[3][1] = ffma2(ap3, w1, accp[3][1]);
            accp[3][2] = ffma2(ap3, w2, accp[3][2]);
            accp[3][3] = ffma2(ap3, w3, accp[3][3]);
        }
    }

    const float4 b4 = *reinterpret_cast<const float4*>(bias + tx * 4);
#pragma unroll
    for (int p = 0; p < 4; p++) {
        float lo[4], hi[4];
#pragma unroll
        for (int c = 0; c < 4; c++) unpack2(accp[p][c], lo[c], hi[c]);

#pragma unroll
        for (int h = 0; h < 2; h++) {
            const int r = rowBase + ty * 8 + 2 * p + h;
            if (r >= N) continue;
            const float* src = h ? hi : lo;
            float4 v;
            v.x = src[0] + b4.x;
            v.y = src[1] + b4.y;
            v.z = src[2] + b4.z;
            v.w = src[3] + b4.w;
            v.x = (v.x > 0.f) ? v.x : 0.01f * v.x;
            v.y = (v.y > 0.f) ? v.y : 0.01f * v.y;
            v.z = (v.z > 0.f) ? v.z : 0.01f * v.z;
            v.w = (v.w > 0.f) ? v.w : 0.01f * v.w;
            if (!pool) {
                *reinterpret_cast<float4*>(out + (size_t)r * DIM + tx * 4) = v;
            } else {
                int g = batch[r];
                atomicAdd(reinterpret_cast<float4*>(pooled + (size_t)g * DIM + tx * 4), v);
            }
        }
    }
}

// ---------------------------------------------------------------------------
__global__ void counts_kernel(const int* __restrict__ batch,
                              float* __restrict__ counts, int N) {
    int i = blockIdx.x * blockDim.x + threadIdx.x;
    if (i < N) atomicAdd(&counts[batch[i]], 1.0f);
}

__global__ void final_kernel(const float* __restrict__ pooled,
                             const float* __restrict__ counts,
                             const float* __restrict__ Wl,
                             const float* __restrict__ bl,
                             float* __restrict__ out) {
    int g = blockIdx.x * blockDim.x + threadIdx.x;
    if (g >= NGRAPH) return;
    float inv = 1.0f / fmaxf(counts[g], 1.0f);
    float acc[8];
#pragma unroll
    for (int c = 0; c < 8; c++) acc[c] = 0.f;
    for (int d = 0; d < DIM; d++) {
        float p = pooled[g * DIM + d];
#pragma unroll
        for (int c = 0; c < 8; c++) acc[c] += p * Wl[d * 8 + c];
    }
#pragma unroll
    for (int c = 0; c < 8; c++) out[g * 8 + c] = bl[c] + inv * acc[c];
}

// ---------------------------------------------------------------------------
extern "C" void kernel_launch(void* const* d_in, const int* in_sizes, int n_in,
                              void* d_out, int out_size) {
    const float* x      = (const float*)d_in[0];
    const int*   ei     = (const int*)d_in[1];
    const float* w      = (const float*)d_in[2];
    const int*   batch  = (const int*)d_in[3];
    const float* W1root = (const float*)d_in[4];
    const float* W1rel  = (const float*)d_in[5];
    const float* b1     = (const float*)d_in[6];
    const float* W2root = (const float*)d_in[7];
    const float* W2rel  = (const float*)d_in[8];
    const float* b2     = (const float*)d_in[9];
    const float* Wl     = (const float*)d_in[10];
    const float* bl     = (const float*)d_in[11];
    float* out = (float*)d_out;

    const int N = in_sizes[0] / DIM;
    const int E = in_sizes[2];

    float *agg, *h1, *pooled, *counts;
    int2* edges; int *deg, *rowstart, *cursor, *blocksum;
    cudaGetSymbolAddress((void**)&agg,      g_agg);
    cudaGetSymbolAddress((void**)&h1,       g_h1);
    cudaGetSymbolAddress((void**)&pooled,   g_pooled);
    cudaGetSymbolAddress((void**)&counts,   g_counts);
    cudaGetSymbolAddress((void**)&edges,    g_edges);
    cudaGetSymbolAddress((void**)&deg,      g_deg);
    cudaGetSymbolAddress((void**)&rowstart, g_rowstart);
    cudaGetSymbolAddress((void**)&cursor,   g_cursor);
    cudaGetSymbolAddress((void**)&blocksum, g_blocksum);

    const int nb = (N + SCANB - 1) / SCANB;

    // ---- CSR build (shared by both layers) ----
    zero_kernel<<<(N + 255) / 256, 256>>>(deg, pooled, counts, N);
    hist_kernel<<<(E + 255) / 256, 256>>>(ei, deg, E);
    scan1_kernel<<<nb, SCANB>>>(deg, rowstart, blocksum, N);
    scan2_kernel<<<1, 128>>>(blocksum, nb);
    scan3_kernel<<<(N + 255) / 256, 256>>>(rowstart, cursor, blocksum, N, E);
    scatter_kernel<<<(E + 255) / 256, 256>>>(ei, w, cursor, edges, E);

    const int gatherBlocks = (N * 32 + 255) / 256;
    const int nodeBlocks = (N + 127) / 128;

    // ---- Layer 1 ----
    gather_kernel<<<gatherBlocks, 256>>>(x, edges, rowstart, agg, N);
    node_kernel<<<nodeBlocks, 256>>>(agg, x, W1rel, W1root, b1,
                                     h1, nullptr, nullptr, N, 0);
    // ---- Layer 2 (pool fused into epilogue) ----
    gather_kernel<<<gatherBlocks, 256>>>(h1, edges, rowstart, agg, N);
    node_kernel<<<nodeBlocks, 256>>>(agg, h1, W2rel, W2root, b2,
                                     nullptr, batch, pooled, N, 1);

    counts_kernel<<<(N + 255) / 256, 256>>>(batch, counts, N);
    final_kernel<<<(NGRAPH + 255) / 256, 256>>>(pooled, counts, Wl, bl, out);
}

// round 11
// speedup vs baseline: 1.3819x; 1.0062x over previous
#include <cuda_runtime.h>
#include <cuda_bf16.h>
#include <cstdint>

// ---------------------------------------------------------------------------
// ConversationalGraph: 2x GraphConv (D=H=64) + leaky_relu + mean-pool + linear
//   layer: out = segsum(x[src]*w -> dst) @ W_rel + b + x @ W_root
// N=100000, E=1250000, 512 graphs, C=8.
// CSR counting-sort + paired-edge float4 warp gather + f32x2 node GEMM.
// ---------------------------------------------------------------------------

#define NMAX   100000
#define EMAX   1250000
#define DIM    64
#define NGRAPH 512
#define SCANB  1024
#define NBLK   ((NMAX + SCANB - 1) / SCANB)   // 98

__device__ float g_agg[NMAX * DIM];
__device__ float g_h1[NMAX * DIM];
__device__ float g_pooled[NGRAPH * DIM];
__device__ float g_counts[NGRAPH];

__device__ alignas(16) int2 g_edges[EMAX];   // (src, w-bits) sorted by dst
__device__ int  g_deg[NMAX];
__device__ int  g_rowstart[NMAX + 1];
__device__ int  g_cursor[NMAX];
__device__ int  g_blocksum[NBLK + 1];

// ---- packed f32x2 helpers --------------------------------------------------
__device__ __forceinline__ uint64_t ffma2(uint64_t a, uint64_t b, uint64_t c) {
    uint64_t d;
    asm("fma.rn.f32x2 %0, %1, %2, %3;" : "=l"(d) : "l"(a), "l"(b), "l"(c));
    return d;
}
__device__ __forceinline__ uint64_t splat2(float f) {
    uint64_t d;
    asm("mov.b64 %0, {%1, %1};" : "=l"(d) : "f"(f));
    return d;
}
__device__ __forceinline__ void unpack2(uint64_t v, float& lo, float& hi) {
    asm("mov.b64 {%0, %1}, %2;" : "=f"(lo), "=f"(hi) : "l"(v));
}

// ---------------------------------------------------------------------------
__global__ void zero_kernel(int* deg, float* pooled, float* counts, int N) {
    int i = blockIdx.x * blockDim.x + threadIdx.x;
    if (i < N) deg[i] = 0;
    if (i < NGRAPH * DIM) pooled[i] = 0.f;
    if (i < NGRAPH) counts[i] = 0.f;
}

// ---------------------------------------------------------------------------
// CSR build: histogram, scan (block-level + fold), scatter (+graph counts)
// ---------------------------------------------------------------------------
__global__ void hist_kernel(const int* __restrict__ ei, int* __restrict__ deg, int E) {
    int e = blockIdx.x * blockDim.x + threadIdx.x;
    if (e < E) atomicAdd(&deg[__ldg(&ei[e + E])], 1);
}

__global__ void scan1_kernel(const int* __restrict__ deg, int* __restrict__ rowstart,
                             int* __restrict__ blocksum, int N) {
    __shared__ int s[SCANB];
    int i = blockIdx.x * SCANB + threadIdx.x;
    int v = (i < N) ? deg[i] : 0;
    s[threadIdx.x] = v;
    __syncthreads();
#pragma unroll
    for (int off = 1; off < SCANB; off <<= 1) {
        int t = (threadIdx.x >= off) ? s[threadIdx.x - off] : 0;
        __syncthreads();
        s[threadIdx.x] += t;
        __syncthreads();
    }
    if (i < N) rowstart[i] = s[threadIdx.x] - v;   // exclusive within block
    if (threadIdx.x == SCANB - 1) blocksum[blockIdx.x] = s[SCANB - 1];
}

// Adds block-level prefix (computed locally from blocksum) to rowstart,
// initializes cursor. Replaces the old separate scan2 launch.
__global__ void scan3_kernel(int* __restrict__ rowstart, int* __restrict__ cursor,
                             const int* __restrict__ blocksum, int N, int E, int nb) {
    __shared__ int s[128];
    const int t = threadIdx.x;
    if (t < 128) {
        // shifted load -> inclusive scan yields exclusive prefix of blocksum
        s[t] = (t > 0 && t - 1 < nb) ? blocksum[t - 1] : 0;
    }
    __syncthreads();
#pragma unroll
    for (int off = 1; off < 128; off <<= 1) {
        int u = (t < 128 && t >= off) ? s[t - off] : 0;
        __syncthreads();
        if (t < 128) s[t] += u;
        __syncthreads();
    }
    int i = blockIdx.x * blockDim.x + t;
    if (i < N) {
        int r = rowstart[i] + s[i >> 10];
        rowstart[i] = r;
        cursor[i] = r;
    }
    if (i == 0) rowstart[N] = E;
}

__global__ void scatter_kernel(const int* __restrict__ ei, const float* __restrict__ w,
                               int* __restrict__ cursor, int2* __restrict__ edges,
                               const int* __restrict__ batch, float* __restrict__ counts,
                               int E, int N) {
    int e = blockIdx.x * blockDim.x + threadIdx.x;
    if (e >= E) return;
    int s = __ldg(&ei[e]);
    int d = __ldg(&ei[e + E]);
    int pos = atomicAdd(&cursor[d], 1);
    edges[pos] = make_int2(s, __float_as_int(__ldg(&w[e])));
    if (e < N) atomicAdd(&counts[__ldg(&batch[e])], 1.0f);   // fused graph counts
}

// ---------------------------------------------------------------------------
// Atomic-free aggregation: agg[n] = sum over incident edges of x[src]*w.
// One warp per node. Half-warp per edge: lanes 0-15 -> edge i, 16-31 -> i+1.
// Each lane covers 4 columns via LDG.128; halves combined with shfl.xor(16).
// ---------------------------------------------------------------------------
__global__ void __launch_bounds__(256)
gather_kernel(const float* __restrict__ x, const int2* __restrict__ edges,
              const int* __restrict__ rowstart, float* __restrict__ agg, int N) {
    int gtid = blockIdx.x * blockDim.x + threadIdx.x;
    int node = gtid >> 5;
    int lane = gtid & 31;
    if (node >= N) return;
    const int half = lane >> 4;
    const int l16 = lane & 15;
    int beg = __ldg(&rowstart[node]);
    int end = __ldg(&rowstart[node + 1]);
    float4 acc = make_float4(0.f, 0.f, 0.f, 0.f);

    int i = beg;
    if ((i & 1) && i < end) {                 // peel to even index (16B align)
        if (!half) {
            int2 ed = __ldg(&edges[i]);
            float wt = __int_as_float(ed.y);
            float4 xv = __ldg(reinterpret_cast<const float4*>(
                x + (size_t)ed.x * DIM + l16 * 4));
            acc.x += wt * xv.x; acc.y += wt * xv.y;
            acc.z += wt * xv.z; acc.w += wt * xv.w;
        }
        i++;
    }
#pragma unroll 2
    for (; i + 1 < end; i += 2) {
        int4 ep = __ldg(reinterpret_cast<const int4*>(edges + i));  // 2 edges
        int   src = half ? ep.z : ep.x;
        float wt  = __int_as_float(half ? ep.w : ep.y);
        float4 xv = __ldg(reinterpret_cast<const float4*>(
            x + (size_t)src * DIM + l16 * 4));
        acc.x += wt * xv.x; acc.y += wt * xv.y;
        acc.z += wt * xv.z; acc.w += wt * xv.w;
    }
    if (i < end) {                            // tail edge
        if (!half) {
            int2 ed = __ldg(&edges[i]);
            float wt = __int_as_float(ed.y);
            float4 xv = __ldg(reinterpret_cast<const float4*>(
                x + (size_t)ed.x * DIM + l16 * 4));
            acc.x += wt * xv.x; acc.y += wt * xv.y;
            acc.z += wt * xv.z; acc.w += wt * xv.w;
        }
    }
    // combine the two halves
    acc.x += __shfl_xor_sync(0xffffffffu, acc.x, 16);
    acc.y += __shfl_xor_sync(0xffffffffu, acc.y, 16);
    acc.z += __shfl_xor_sync(0xffffffffu, acc.z, 16);
    acc.w += __shfl_xor_sync(0xffffffffu, acc.w, 16);
    if (!half)
        *reinterpret_cast<float4*>(agg + (size_t)node * DIM + l16 * 4) = acc;
}

// ---------------------------------------------------------------------------
// Node kernel: out = leaky( Aagg @ Wrel + Ax @ Wroot + b )
// [N x 128] @ [128 x 64] GEMM via packed fma.rn.f32x2.
// Block tile 128 rows x 64 cols, 256 threads, per-thread 8x4 micro-tile.
// pool!=0: accumulate rows into pooled[batch[row]] instead of storing.
// ---------------------------------------------------------------------------
__global__ void __launch_bounds__(256)
node_kernel(const float* __restrict__ Aagg, const float* __restrict__ Ax,
            const float* __restrict__ Wrel, const float* __restrict__ Wroot,
            const float* __restrict__ bias,
            float* __restrict__ out,
            const int* __restrict__ batch,
            float* __restrict__ pooled,
            int N, int pool) {
    __shared__ float As[16][136];   // [k][row], 128 rows + pad
    __shared__ float Ws[16][64];    // [k][col]

    const int tid = threadIdx.x;
    const int tx = tid & 15;        // col group: cols tx*4 .. +3
    const int ty = tid >> 4;        // row group: rows ty*8 .. +7
    const int rowBase = blockIdx.x * 128;

    const int lr  = tid >> 1;
    const int lks = (tid & 1) * 8;
    const int wk = tid >> 4;
    const int wj = (tid & 15) * 4;

    uint64_t accp[4][4];            // [row-pair][col]
#pragma unroll
    for (int p = 0; p < 4; p++)
#pragma unroll
        for (int c = 0; c < 4; c++) accp[p][c] = 0ull;

#pragma unroll
    for (int kc = 0; kc < 8; kc++) {
        const int kk = (kc & 3) * 16;
        const float* Asrc = (kc < 4) ? Aagg : Ax;
        const float* Wsrc = (kc < 4) ? Wrel : Wroot;

        const int arow = rowBase + lr;
        float4 av0 = make_float4(0.f, 0.f, 0.f, 0.f);
        float4 av1 = av0;
        if (arow < N) {
            const float* base = Asrc + (size_t)arow * DIM + kk + lks;
            av0 = *reinterpret_cast<const float4*>(base);
            av1 = *reinterpret_cast<const float4*>(base + 4);
        }
        float4 wv = *reinterpret_cast<const float4*>(Wsrc + (wk + kk) * DIM + wj);

        __syncthreads();
        As[lks + 0][lr] = av0.x;
        As[lks + 1][lr] = av0.y;
        As[lks + 2][lr] = av0.z;
        As[lks + 3][lr] = av0.w;
        As[lks + 4][lr] = av1.x;
        As[lks + 5][lr] = av1.y;
        As[lks + 6][lr] = av1.z;
        As[lks + 7][lr] = av1.w;
        *reinterpret_cast<float4*>(&Ws[wk][wj]) = wv;
        __syncthreads();

#pragma unroll
        for (int k = 0; k < 16; k++) {
            const uint64_t* arow2 =
                reinterpret_cast<const uint64_t*>(&As[k][ty * 8]);
            uint64_t ap0 = arow2[0];
            uint64_t ap1 = arow2[1];
            uint64_t ap2 = arow2[2];
            uint64_t ap3 = arow2[3];
            float4 wq = *reinterpret_cast<float4*>(&Ws[k][tx * 4]);
            uint64_t w0 = splat2(wq.x);
            uint64_t w1 = splat2(wq.y);
            uint64_t w2 = splat2(wq.z);
            uint64_t w3 = splat2(wq.w);
            accp[0][0] = ffma2(ap0, w0, accp[0][0]);
            accp[0][1] = ffma2(ap0, w1, accp[0][1]);
            accp[0][2] = ffma2(ap0, w2, accp[0][2]);
            accp[0][3] = ffma2(ap0, w3, accp[0][3]);
            accp[1][0] = ffma2(ap1, w0, accp[1][0]);
            accp[1][1] = ffma2(ap1, w1, accp[1][1]);
            accp[1][2] = ffma2(ap1, w2, accp[1][2]);
            accp[1][3] = ffma2(ap1, w3, accp[1][3]);
            accp[2][0] = ffma2(ap2, w0, accp[2][0]);
            accp[2][1] = ffma2(ap2, w1, accp[2][1]);
            accp[2][2] = ffma2(ap2, w2, accp[2][2]);
            accp[2][3] = ffma2(ap2, w3, accp[2][3]);
            accp[3][0] = ffma2(ap3, w0, accp[3][0]);
            accp[3][1] = ffma2(ap3, w1, accp[3][1]);
            accp[3][2] = ffma2(ap3, w2, accp[3][2]);
            accp[3][3] = ffma2(ap3, w3, accp[3][3]);
        }
    }

    const float4 b4 = *reinterpret_cast<const float4*>(bias + tx * 4);
#pragma unroll
    for (int p = 0; p < 4; p++) {
        float lo[4], hi[4];
#pragma unroll
        for (int c = 0; c < 4; c++) unpack2(accp[p][c], lo[c], hi[c]);

#pragma unroll
        for (int h = 0; h < 2; h++) {
            const int r = rowBase + ty * 8 + 2 * p + h;
            if (r >= N) continue;
            const float* src = h ? hi : lo;
            float4 v;
            v.x = src[0] + b4.x;
            v.y = src[1] + b4.y;
            v.z = src[2] + b4.z;
            v.w = src[3] + b4.w;
            v.x = (v.x > 0.f) ? v.x : 0.01f * v.x;
            v.y = (v.y > 0.f) ? v.y : 0.01f * v.y;
            v.z = (v.z > 0.f) ? v.z : 0.01f * v.z;
            v.w = (v.w > 0.f) ? v.w : 0.01f * v.w;
            if (!pool) {
                *reinterpret_cast<float4*>(out + (size_t)r * DIM + tx * 4) = v;
            } else {
                int g = batch[r];
                atomicAdd(reinterpret_cast<float4*>(pooled + (size_t)g * DIM + tx * 4), v);
            }
        }
    }
}

// ---------------------------------------------------------------------------
__global__ void final_kernel(const float* __restrict__ pooled,
                             const float* __restrict__ counts,
                             const float* __restrict__ Wl,
                             const float* __restrict__ bl,
                             float* __restrict__ out) {
    int g = blockIdx.x * blockDim.x + threadIdx.x;
    if (g >= NGRAPH) return;
    float inv = 1.0f / fmaxf(counts[g], 1.0f);
    float acc[8];
#pragma unroll
    for (int c = 0; c < 8; c++) acc[c] = 0.f;
    for (int d = 0; d < DIM; d++) {
        float p = pooled[g * DIM + d];
#pragma unroll
        for (int c = 0; c < 8; c++) acc[c] += p * Wl[d * 8 + c];
    }
#pragma unroll
    for (int c = 0; c < 8; c++) out[g * 8 + c] = bl[c] + inv * acc[c];
}

// ---------------------------------------------------------------------------
extern "C" void kernel_launch(void* const* d_in, const int* in_sizes, int n_in,
                              void* d_out, int out_size) {
    const float* x      = (const float*)d_in[0];
    const int*   ei     = (const int*)d_in[1];
    const float* w      = (const float*)d_in[2];
    const int*   batch  = (const int*)d_in[3];
    const float* W1root = (const float*)d_in[4];
    const float* W1rel  = (const float*)d_in[5];
    const float* b1     = (const float*)d_in[6];
    const float* W2root = (const float*)d_in[7];
    const float* W2rel  = (const float*)d_in[8];
    const float* b2     = (const float*)d_in[9];
    const float* Wl     = (const float*)d_in[10];
    const float* bl     = (const float*)d_in[11];
    float* out = (float*)d_out;

    const int N = in_sizes[0] / DIM;
    const int E = in_sizes[2];

    float *agg, *h1, *pooled, *counts;
    int2* edges; int *deg, *rowstart, *cursor, *blocksum;
    cudaGetSymbolAddress((void**)&agg,      g_agg);
    cudaGetSymbolAddress((void**)&h1,       g_h1);
    cudaGetSymbolAddress((void**)&pooled,   g_pooled);
    cudaGetSymbolAddress((void**)&counts,   g_counts);
    cudaGetSymbolAddress((void**)&edges,    g_edges);
    cudaGetSymbolAddress((void**)&deg,      g_deg);
    cudaGetSymbolAddress((void**)&rowstart, g_rowstart);
    cudaGetSymbolAddress((void**)&cursor,   g_cursor);
    cudaGetSymbolAddress((void**)&blocksum, g_blocksum);

    const int nb = (N + SCANB - 1) / SCANB;

    // ---- CSR build (shared by both layers) ----
    zero_kernel<<<(N + 255) / 256, 256>>>(deg, pooled, counts, N);
    hist_kernel<<<(E + 255) / 256, 256>>>(ei, deg, E);
    scan1_kernel<<<nb, SCANB>>>(deg, rowstart, blocksum, N);
    scan3_kernel<<<(N + 255) / 256, 256>>>(rowstart, cursor, blocksum, N, E, nb);
    scatter_kernel<<<(E + 255) / 256, 256>>>(ei, w, cursor, edges, batch, counts, E, N);

    const int gatherBlocks = (N * 32 + 255) / 256;
    const int nodeBlocks = (N + 127) / 128;

    // ---- Layer 1 ----
    gather_kernel<<<gatherBlocks, 256>>>(x, edges, rowstart, agg, N);
    node_kernel<<<nodeBlocks, 256>>>(agg, x, W1rel, W1root, b1,
                                     h1, nullptr, nullptr, N, 0);
    // ---- Layer 2 (pool fused into epilogue) ----
    gather_kernel<<<gatherBlocks, 256>>>(h1, edges, rowstart, agg, N);
    node_kernel<<<nodeBlocks, 256>>>(agg, h1, W2rel, W2root, b2,
                                     nullptr, batch, pooled, N, 1);

    final_kernel<<<(NGRAPH + 255) / 256, 256>>>(pooled, counts, Wl, bl, out);
}

// round 13
// speedup vs baseline: 1.4261x; 1.0320x over previous
#include <cuda_runtime.h>
#include <cuda_fp16.h>
#include <cstdint>

// ---------------------------------------------------------------------------
// ConversationalGraph: 2x GraphConv (D=H=64) + leaky_relu + mean-pool + linear
//   layer: out = segsum(x[src]*w -> dst) @ W_rel + b + x @ W_root
// N=100000, E=1250000, 512 graphs, C=8.
// CSR counting-sort; fp16 feature storage for the gather operand (x, h1);
// fp32 accumulation everywhere; f32x2 packed-FMA node GEMM.
// ---------------------------------------------------------------------------

#define NMAX   100000
#define EMAX   1250000
#define DIM    64
#define NGRAPH 512
#define SCANB  1024
#define NBLK   ((NMAX + SCANB - 1) / SCANB)   // 98

__device__ float  g_agg[NMAX * DIM];
__device__ __half g_xh[NMAX * DIM];
__device__ __half g_h1h[NMAX * DIM];
__device__ float  g_pooled[NGRAPH * DIM];
__device__ float  g_counts[NGRAPH];

__device__ alignas(16) int2 g_edges[EMAX];   // (src, w-bits) sorted by dst
__device__ int  g_deg[NMAX];
__device__ int  g_rowstart[NMAX + 1];
__device__ int  g_cursor[NMAX];
__device__ int  g_blocksum[NBLK + 1];

// ---- packed f32x2 helpers --------------------------------------------------
__device__ __forceinline__ uint64_t ffma2(uint64_t a, uint64_t b, uint64_t c) {
    uint64_t d;
    asm("fma.rn.f32x2 %0, %1, %2, %3;" : "=l"(d) : "l"(a), "l"(b), "l"(c));
    return d;
}
__device__ __forceinline__ uint64_t splat2(float f) {
    uint64_t d;
    asm("mov.b64 %0, {%1, %1};" : "=l"(d) : "f"(f));
    return d;
}
__device__ __forceinline__ void unpack2(uint64_t v, float& lo, float& hi) {
    asm("mov.b64 {%0, %1}, %2;" : "=f"(lo), "=f"(hi) : "l"(v));
}

// ---------------------------------------------------------------------------
__global__ void zero_kernel(int* deg, float* pooled, float* counts, int N) {
    int i = blockIdx.x * blockDim.x + threadIdx.x;
    if (i < N) deg[i] = 0;
    if (i < NGRAPH * DIM) pooled[i] = 0.f;
    if (i < NGRAPH) counts[i] = 0.f;
}

// Convert x (fp32) -> x_half.  half2 stores.
__global__ void convert_kernel(const float* __restrict__ x, __half* __restrict__ xh,
                               int n2 /* = N*DIM/2 */) {
    int i = blockIdx.x * blockDim.x + threadIdx.x;
    if (i < n2) {
        float2 v = reinterpret_cast<const float2*>(x)[i];
        reinterpret_cast<__half2*>(xh)[i] = __floats2half2_rn(v.x, v.y);
    }
}

// ---------------------------------------------------------------------------
// CSR build: histogram, scan (block-level + fold), scatter (+graph counts)
// ---------------------------------------------------------------------------
__global__ void hist_kernel(const int* __restrict__ ei, int* __restrict__ deg, int E) {
    int e = blockIdx.x * blockDim.x + threadIdx.x;
    if (e < E) atomicAdd(&deg[__ldg(&ei[e + E])], 1);
}

__global__ void scan1_kernel(const int* __restrict__ deg, int* __restrict__ rowstart,
                             int* __restrict__ blocksum, int N) {
    __shared__ int s[SCANB];
    int i = blockIdx.x * SCANB + threadIdx.x;
    int v = (i < N) ? deg[i] : 0;
    s[threadIdx.x] = v;
    __syncthreads();
#pragma unroll
    for (int off = 1; off < SCANB; off <<= 1) {
        int t = (threadIdx.x >= off) ? s[threadIdx.x - off] : 0;
        __syncthreads();
        s[threadIdx.x] += t;
        __syncthreads();
    }
    if (i < N) rowstart[i] = s[threadIdx.x] - v;   // exclusive within block
    if (threadIdx.x == SCANB - 1) blocksum[blockIdx.x] = s[SCANB - 1];
}

// Adds block-level prefix (computed locally from blocksum) to rowstart,
// initializes cursor.
__global__ void scan3_kernel(int* __restrict__ rowstart, int* __restrict__ cursor,
                             const int* __restrict__ blocksum, int N, int E, int nb) {
    __shared__ int s[128];
    const int t = threadIdx.x;
    if (t < 128) {
        s[t] = (t > 0 && t - 1 < nb) ? blocksum[t - 1] : 0;
    }
    __syncthreads();
#pragma unroll
    for (int off = 1; off < 128; off <<= 1) {
        int u = (t < 128 && t >= off) ? s[t - off] : 0;
        __syncthreads();
        if (t < 128) s[t] += u;
        __syncthreads();
    }
    int i = blockIdx.x * blockDim.x + t;
    if (i < N) {
        int r = rowstart[i] + s[i >> 10];
        rowstart[i] = r;
        cursor[i] = r;
    }
    if (i == 0) rowstart[N] = E;
}

__global__ void scatter_kernel(const int* __restrict__ ei, const float* __restrict__ w,
                               int* __restrict__ cursor, int2* __restrict__ edges,
                               const int* __restrict__ batch, float* __restrict__ counts,
                               int E, int N) {
    int e = blockIdx.x * blockDim.x + threadIdx.x;
    if (e >= E) return;
    int s = __ldg(&ei[e]);
    int d = __ldg(&ei[e + E]);
    int pos = atomicAdd(&cursor[d], 1);
    edges[pos] = make_int2(s, __float_as_int(__ldg(&w[e])));
    if (e < N) atomicAdd(&counts[__ldg(&batch[e])], 1.0f);   // fused graph counts
}

// ---------------------------------------------------------------------------
// Atomic-free aggregation from fp16 features, fp32 accumulate.
// One warp per node; lane covers cols {2*lane, 2*lane+1} via one half2 load
// (128B per edge per warp). Result stored fp32.
// ---------------------------------------------------------------------------
__global__ void __launch_bounds__(256)
gather_kernel(const __half* __restrict__ xh, const int2* __restrict__ edges,
              const int* __restrict__ rowstart, float* __restrict__ agg, int N) {
    int gtid = blockIdx.x * blockDim.x + threadIdx.x;
    int node = gtid >> 5;
    int lane = gtid & 31;
    if (node >= N) return;
    int beg = __ldg(&rowstart[node]);
    int end = __ldg(&rowstart[node + 1]);
    float a0 = 0.f, a1 = 0.f;
#pragma unroll 4
    for (int i = beg; i < end; i++) {
        int2 ed = __ldg(&edges[i]);                 // broadcast across warp
        float wt = __int_as_float(ed.y);
        __half2 hv = __ldg(reinterpret_cast<const __half2*>(
            xh + (size_t)ed.x * DIM) + lane);
        float2 xv = __half22float2(hv);
        a0 += wt * xv.x;
        a1 += wt * xv.y;
    }
    *reinterpret_cast<float2*>(agg + (size_t)node * DIM + lane * 2) =
        make_float2(a0, a1);
}

// ---------------------------------------------------------------------------
// Node kernel: res = leaky( Aagg @ Wrel + Axh @ Wroot + b )
// [N x 128] @ [128 x 64] GEMM via packed fma.rn.f32x2.
// A K-chunks 0-63 come from agg (fp32); 64-127 from fp16 features (converted
// at smem fill). Output: pool==0 -> half feature rows (outh); pool==1 ->
// fp32 atomic accumulation into pooled[batch[row]].
// ---------------------------------------------------------------------------
__global__ void __launch_bounds__(256)
node_kernel(const float* __restrict__ Aagg, const __half* __restrict__ Axh,
            const float* __restrict__ Wrel, const float* __restrict__ Wroot,
            const float* __restrict__ bias,
            __half* __restrict__ outh,
            const int* __restrict__ batch,
            float* __restrict__ pooled,
            int N, int pool) {
    __shared__ float As[16][136];   // [k][row], 128 rows + pad
    __shared__ float Ws[16][64];    // [k][col]

    const int tid = threadIdx.x;
    const int tx = tid & 15;        // col group: cols tx*4 .. +3
    const int ty = tid >> 4;        // row group: rows ty*8 .. +7
    const int rowBase = blockIdx.x * 128;

    const int lr  = tid >> 1;          // A row 0..127
    const int lks = (tid & 1) * 8;     // k offset {0,8}
    const int wk = tid >> 4;
    const int wj = (tid & 15) * 4;

    uint64_t accp[4][4];            // [row-pair][col]
#pragma unroll
    for (int p = 0; p < 4; p++)
#pragma unroll
        for (int c = 0; c < 4; c++) accp[p][c] = 0ull;

#pragma unroll
    for (int kc = 0; kc < 8; kc++) {
        const int kk = (kc & 3) * 16;
        const float* Wsrc = (kc < 4) ? Wrel : Wroot;

        const int arow = rowBase + lr;
        float4 av0 = make_float4(0.f, 0.f, 0.f, 0.f);
        float4 av1 = av0;
        if (arow < N) {
            if (kc < 4) {
                const float* base = Aagg + (size_t)arow * DIM + kk + lks;
                av0 = *reinterpret_cast<const float4*>(base);
                av1 = *reinterpret_cast<const float4*>(base + 4);
            } else {
                const __half2* base = reinterpret_cast<const __half2*>(
                    Axh + (size_t)arow * DIM + kk + lks);
                __half2 h[4];
                *reinterpret_cast<uint4*>(h) =
                    *reinterpret_cast<const uint4*>(base);   // 8 halves
                float2 f0 = __half22float2(h[0]);
                float2 f1 = __half22float2(h[1]);
                float2 f2 = __half22float2(h[2]);
                float2 f3 = __half22float2(h[3]);
                av0 = make_float4(f0.x, f0.y, f1.x, f1.y);
                av1 = make_float4(f2.x, f2.y, f3.x, f3.y);
            }
        }
        float4 wv = *reinterpret_cast<const float4*>(Wsrc + (wk + kk) * DIM + wj);

        __syncthreads();
        As[lks + 0][lr] = av0.x;
        As[lks + 1][lr] = av0.y;
        As[lks + 2][lr] = av0.z;
        As[lks + 3][lr] = av0.w;
        As[lks + 4][lr] = av1.x;
        As[lks + 5][lr] = av1.y;
        As[lks + 6][lr] = av1.z;
        As[lks + 7][lr] = av1.w;
        *reinterpret_cast<float4*>(&Ws[wk][wj]) = wv;
        __syncthreads();

#pragma unroll
        for (int k = 0; k < 16; k++) {
            const uint64_t* arow2 =
                reinterpret_cast<const uint64_t*>(&As[k][ty * 8]);
            uint64_t ap0 = arow2[0];
            uint64_t ap1 = arow2[1];
            uint64_t ap2 = arow2[2];
            uint64_t ap3 = arow2[3];
            float4 wq = *reinterpret_cast<float4*>(&Ws[k][tx * 4]);
            uint64_t w0 = splat2(wq.x);
            uint64_t w1 = splat2(wq.y);
            uint64_t w2 = splat2(wq.z);
            uint64_t w3 = splat2(wq.w);
            accp[0][0] = ffma2(ap0, w0, accp[0][0]);
            accp[0][1] = ffma2(ap0, w1, accp[0][1]);
            accp[0][2] = ffma2(ap0, w2, accp[0][2]);
            accp[0][3] = ffma2(ap0, w3, accp[0][3]);
            accp[1][0] = ffma2(ap1, w0, accp[1][0]);
            accp[1][1] = ffma2(ap1, w1, accp[1][1]);
            accp[1][2] = ffma2(ap1, w2, accp[1][2]);
            accp[1][3] = ffma2(ap1, w3, accp[1][3]);
            accp[2][0] = ffma2(ap2, w0, accp[2][0]);
            accp[2][1] = ffma2(ap2, w1, accp[2][1]);
            accp[2][2] = ffma2(ap2, w2, accp[2][2]);
            accp[2][3] = ffma2(ap2, w3, accp[2][3]);
            accp[3][0] = ffma2(ap3, w0, accp[3][0]);
            accp[3][1] = ffma2(ap3, w1, accp[3][1]);
            accp[3][2] = ffma2(ap3, w2, accp[3][2]);
            accp[3][3] = ffma2(ap3, w3, accp[3][3]);
        }
    }

    const float4 b4 = *reinterpret_cast<const float4*>(bias + tx * 4);
#pragma unroll
    for (int p = 0; p < 4; p++) {
        float lo[4], hi[4];
#pragma unroll
        for (int c = 0; c < 4; c++) unpack2(accp[p][c], lo[c], hi[c]);

#pragma unroll
        for (int h = 0; h < 2; h++) {
            const int r = rowBase + ty * 8 + 2 * p + h;
            if (r >= N) continue;
            const float* src = h ? hi : lo;
            float v0 = src[0] + b4.x;
            float v1 = src[1] + b4.y;
            float v2 = src[2] + b4.z;
            float v3 = src[3] + b4.w;
            v0 = (v0 > 0.f) ? v0 : 0.01f * v0;
            v1 = (v1 > 0.f) ? v1 : 0.01f * v1;
            v2 = (v2 > 0.f) ? v2 : 0.01f * v2;
            v3 = (v3 > 0.f) ? v3 : 0.01f * v3;
            if (!pool) {
                __half2 h01 = __floats2half2_rn(v0, v1);
                __half2 h23 = __floats2half2_rn(v2, v3);
                uint2 packed = make_uint2(
                    *reinterpret_cast<uint32_t*>(&h01),
                    *reinterpret_cast<uint32_t*>(&h23));
                *reinterpret_cast<uint2*>(outh + (size_t)r * DIM + tx * 4) = packed;
            } else {
                int g = batch[r];
                float4 v = make_float4(v0, v1, v2, v3);
                atomicAdd(reinterpret_cast<float4*>(pooled + (size_t)g * DIM + tx * 4), v);
            }
        }
    }
}

// ---------------------------------------------------------------------------
__global__ void final_kernel(const float* __restrict__ pooled,
                             const float* __restrict__ counts,
                             const float* __restrict__ Wl,
                             const float* __restrict__ bl,
                             float* __restrict__ out) {
    int g = blockIdx.x * blockDim.x + threadIdx.x;
    if (g >= NGRAPH) return;
    float inv = 1.0f / fmaxf(counts[g], 1.0f);
    float acc[8];
#pragma unroll
    for (int c = 0; c < 8; c++) acc[c] = 0.f;
    for (int d = 0; d < DIM; d++) {
        float p = pooled[g * DIM + d];
#pragma unroll
        for (int c = 0; c < 8; c++) acc[c] += p * Wl[d * 8 + c];
    }
#pragma unroll
    for (int c = 0; c < 8; c++) out[g * 8 + c] = bl[c] + inv * acc[c];
}

// ---------------------------------------------------------------------------
extern "C" void kernel_launch(void* const* d_in, const int* in_sizes, int n_in,
                              void* d_out, int out_size) {
    const float* x      = (const float*)d_in[0];
    const int*   ei     = (const int*)d_in[1];
    const float* w      = (const float*)d_in[2];
    const int*   batch  = (const int*)d_in[3];
    const float* W1root = (const float*)d_in[4];
    const float* W1rel  = (const float*)d_in[5];
    const float* b1     = (const float*)d_in[6];
    const float* W2root = (const float*)d_in[7];
    const float* W2rel  = (const float*)d_in[8];
    const float* b2     = (const float*)d_in[9];
    const float* Wl     = (const float*)d_in[10];
    const float* bl     = (const float*)d_in[11];
    float* out = (float*)d_out;

    const int N = in_sizes[0] / DIM;
    const int E = in_sizes[2];

    float *agg, *pooled, *counts;
    __half *xh, *h1h;
    int2* edges; int *deg, *rowstart, *cursor, *blocksum;
    cudaGetSymbolAddress((void**)&agg,      g_agg);
    cudaGetSymbolAddress((void**)&xh,       g_xh);
    cudaGetSymbolAddress((void**)&h1h,      g_h1h);
    cudaGetSymbolAddress((void**)&pooled,   g_pooled);
    cudaGetSymbolAddress((void**)&counts,   g_counts);
    cudaGetSymbolAddress((void**)&edges,    g_edges);
    cudaGetSymbolAddress((void**)&deg,      g_deg);
    cudaGetSymbolAddress((void**)&rowstart, g_rowstart);
    cudaGetSymbolAddress((void**)&cursor,   g_cursor);
    cudaGetSymbolAddress((void**)&blocksum, g_blocksum);

    const int nb = (N + SCANB - 1) / SCANB;
    const int n2 = N * DIM / 2;

    // ---- CSR build + fp16 feature copy ----
    zero_kernel<<<(N + 255) / 256, 256>>>(deg, pooled, counts, N);
    convert_kernel<<<(n2 + 255) / 256, 256>>>(x, xh, n2);
    hist_kernel<<<(E + 255) / 256, 256>>>(ei, deg, E);
    scan1_kernel<<<nb, SCANB>>>(deg, rowstart, blocksum, N);
    scan3_kernel<<<(N + 255) / 256, 256>>>(rowstart, cursor, blocksum, N, E, nb);
    scatter_kernel<<<(E + 255) / 256, 256>>>(ei, w, cursor, edges, batch, counts, E, N);

    const int gatherBlocks = (N * 32 + 255) / 256;
    const int nodeBlocks = (N + 127) / 128;

    // ---- Layer 1 ----
    gather_kernel<<<gatherBlocks, 256>>>(xh, edges, rowstart, agg, N);
    node_kernel<<<nodeBlocks, 256>>>(agg, xh, W1rel, W1root, b1,
                                     h1h, nullptr, nullptr, N, 0);
    // ---- Layer 2 (pool fused into epilogue) ----
    gather_kernel<<<gatherBlocks, 256>>>(h1h, edges, rowstart, agg, N);
    node_kernel<<<nodeBlocks, 256>>>(agg, h1h, W2rel, W2root, b2,
                                     nullptr, batch, pooled, N, 1);

    final_kernel<<<(NGRAPH + 255) / 256, 256>>>(pooled, counts, Wl, bl, out);
}